// round 1
// baseline (speedup 1.0000x reference)
#include <cuda_runtime.h>

// ---------------------------------------------------------------------------
// Linformer block, fp32 baseline:
//   K1: qkv = x @ W_qkv                      (SGEMM, FFMA2 packed fp32)
//   K2: per-batch attention middle (attn_sel sigmoid, E/F low-rank, softmax)
//   K3: out = ctx @ W_proj^T + b_proj        (SGEMM^T, FFMA2 packed fp32)
// Outputs packed into d_out: [B*N*C] main out, then [B*H*H] attn_sel_sig.
// ---------------------------------------------------------------------------

#define BDIM  8192
#define NTOK  4
#define CDIM  1024
#define HDIM  16
#define DDIM  64
#define PDIM  4
#define MTOK  (BDIM * NTOK)          // 32768 tokens
#define SCALE_F 0.125f               // 64^-0.5

// Scratch (device globals: allocation-free per harness rules)
__device__ float g_qkv[(size_t)MTOK * 3 * CDIM];   // [M, 3C]
__device__ float g_ctx[(size_t)MTOK * CDIM];       // [M, C]

// ---------------- packed f32x2 helpers (sm_103a FFMA2 path) ----------------
__device__ __forceinline__ unsigned long long pack_ff(float x, float y) {
    unsigned long long r;
    asm("mov.b64 %0, {%1, %2};" : "=l"(r) : "f"(x), "f"(y));
    return r;
}
__device__ __forceinline__ void unpack_ff(unsigned long long v, float& x, float& y) {
    asm("mov.b64 {%0, %1}, %2;" : "=f"(x), "=f"(y) : "l"(v));
}
__device__ __forceinline__ void ffma2(unsigned long long& d,
                                      unsigned long long a, unsigned long long b) {
    asm("fma.rn.f32x2 %0, %1, %2, %0;" : "+l"(d) : "l"(a), "l"(b));
}

// ---------------------------------------------------------------------------
// SGEMM: C[M,N] = A[M,K] * B (+bias). BT=false: B is [K,N] row-major.
// BT=true: B is [N,K] row-major (i.e. multiply by B^T). 128x128 tile, BK=16,
// 256 threads, 8x8 per thread, inner loop in fma.rn.f32x2.
// M,N multiples of 128; K multiple of 16. No bounds checks.
// ---------------------------------------------------------------------------
template<bool BT, bool BIAS>
__global__ __launch_bounds__(256, 2)
void sgemm_kernel(const float* __restrict__ A, const float* __restrict__ Bm,
                  const float* __restrict__ bias, float* __restrict__ Cout,
                  int M, int N, int K)
{
    __shared__ float As[16][132];   // [k][m], pad 132 floats (528B, 16B-aligned rows)
    __shared__ float Bs[16][132];   // [k][n]

    const int tid = threadIdx.x;
    const int tx = tid & 15, ty = tid >> 4;
    const int m0 = blockIdx.y * 128, n0 = blockIdx.x * 128;

    unsigned long long acc[8][4];
    #pragma unroll
    for (int i = 0; i < 8; i++)
        #pragma unroll
        for (int j = 0; j < 4; j++) acc[i][j] = 0ULL;

    for (int k0 = 0; k0 < K; k0 += 16) {
        // A tile 128x16, stored transposed As[k][m]
        #pragma unroll
        for (int l = 0; l < 2; l++) {
            int idx = tid + l * 256;          // 512 float4s
            int row = idx >> 2;               // 0..127 (m)
            int c4  = (idx & 3) << 2;         // 0,4,8,12 (k)
            float4 v = *reinterpret_cast<const float4*>(
                A + (size_t)(m0 + row) * K + k0 + c4);
            As[c4 + 0][row] = v.x; As[c4 + 1][row] = v.y;
            As[c4 + 2][row] = v.z; As[c4 + 3][row] = v.w;
        }
        if (!BT) {
            // B tile 16x128 row-major -> Bs[k][n] direct
            #pragma unroll
            for (int l = 0; l < 2; l++) {
                int idx = tid + l * 256;
                int row = idx >> 5;           // 0..15 (k)
                int c4  = (idx & 31) << 2;    // 0..124 (n)
                float4 v = *reinterpret_cast<const float4*>(
                    Bm + (size_t)(k0 + row) * N + n0 + c4);
                *reinterpret_cast<float4*>(&Bs[row][c4]) = v;
            }
        } else {
            // B is [N,K]: load 128 n-rows x 16 k, scatter transposed into Bs[k][n]
            #pragma unroll
            for (int l = 0; l < 2; l++) {
                int idx = tid + l * 256;
                int jj = idx >> 2;            // 0..127 (n)
                int c4 = (idx & 3) << 2;      // 0,4,8,12 (k)
                float4 v = *reinterpret_cast<const float4*>(
                    Bm + (size_t)(n0 + jj) * K + k0 + c4);
                Bs[c4 + 0][jj] = v.x; Bs[c4 + 1][jj] = v.y;
                Bs[c4 + 2][jj] = v.z; Bs[c4 + 3][jj] = v.w;
            }
        }
        __syncthreads();

        #pragma unroll
        for (int kk = 0; kk < 16; kk++) {
            float4 a0 = *reinterpret_cast<const float4*>(&As[kk][ty * 8]);
            float4 a1 = *reinterpret_cast<const float4*>(&As[kk][ty * 8 + 4]);
            float4 b0 = *reinterpret_cast<const float4*>(&Bs[kk][tx * 8]);
            float4 b1 = *reinterpret_cast<const float4*>(&Bs[kk][tx * 8 + 4]);
            unsigned long long bp[4];
            bp[0] = pack_ff(b0.x, b0.y); bp[1] = pack_ff(b0.z, b0.w);
            bp[2] = pack_ff(b1.x, b1.y); bp[3] = pack_ff(b1.z, b1.w);
            float av[8] = {a0.x, a0.y, a0.z, a0.w, a1.x, a1.y, a1.z, a1.w};
            #pragma unroll
            for (int i = 0; i < 8; i++) {
                unsigned long long ap = pack_ff(av[i], av[i]);
                #pragma unroll
                for (int j = 0; j < 4; j++) ffma2(acc[i][j], ap, bp[j]);
            }
        }
        __syncthreads();
    }

    #pragma unroll
    for (int i = 0; i < 8; i++) {
        int m = m0 + ty * 8 + i;
        float o[8];
        #pragma unroll
        for (int j = 0; j < 4; j++) unpack_ff(acc[i][j], o[2 * j], o[2 * j + 1]);
        if (BIAS) {
            #pragma unroll
            for (int j = 0; j < 8; j++) o[j] += __ldg(bias + n0 + tx * 8 + j);
        }
        *reinterpret_cast<float4*>(Cout + (size_t)m * N + n0 + tx * 8) =
            make_float4(o[0], o[1], o[2], o[3]);
        *reinterpret_cast<float4*>(Cout + (size_t)m * N + n0 + tx * 8 + 4) =
            make_float4(o[4], o[5], o[6], o[7]);
    }
}

// ---------------------------------------------------------------------------
// Middle kernel: one CTA (256 threads) per batch b.
//   qkv row layout per token: [q(1024) | k(1024) | v(1024)], col = h*64+d.
//   attn_sel[b,h,g]  = sigmoid(SCALE * q[b,h,tok1,:] . k[b,g,tok2,:])
//   k_low[p,c] = sum_n k[n,c]*W_E[p,n];  v_low likewise with W_F
//   attn[n,p] = softmax_p(SCALE * q[n, h*64: ] . k_low[p, h*64:])
//   ctx[b,n, h*64+d] = sum_p attn[n,p] * v_low[p, h*64+d]
// ---------------------------------------------------------------------------
__global__ __launch_bounds__(256)
void attn_mid_kernel(const float* __restrict__ W_E, const float* __restrict__ W_F,
                     float* __restrict__ attn_sel)
{
    __shared__ float s_q[NTOK][CDIM];       // 16 KB
    __shared__ float s_klow[PDIM][CDIM];    // 16 KB
    __shared__ float s_vlow[PDIM][CDIM];    // 16 KB  (total = 48 KB exactly)

    const int b = blockIdx.x;
    const int tid = threadIdx.x;
    const float* base = g_qkv + (size_t)b * NTOK * 3 * CDIM;

    // load q for all 4 tokens (vectorized)
    for (int i = tid; i < NTOK * CDIM / 4; i += 256) {
        int n = i >> 8;
        int c4 = (i & 255) << 2;
        *reinterpret_cast<float4*>(&s_q[n][c4]) =
            *reinterpret_cast<const float4*>(base + (size_t)n * 3 * CDIM + c4);
    }

    // E/F weights to registers
    float we[PDIM * NTOK], wf[PDIM * NTOK];
    #pragma unroll
    for (int i = 0; i < PDIM * NTOK; i++) {
        we[i] = __ldg(W_E + i);
        wf[i] = __ldg(W_F + i);
    }

    // k_low / v_low straight from global k/v rows (each row reused n-times in L1)
    for (int c = tid; c < CDIM; c += 256) {
        float sk[PDIM] = {0.f, 0.f, 0.f, 0.f};
        float sv[PDIM] = {0.f, 0.f, 0.f, 0.f};
        #pragma unroll
        for (int n = 0; n < NTOK; n++) {
            float kn = base[(size_t)n * 3 * CDIM + CDIM + c];
            float vn = base[(size_t)n * 3 * CDIM + 2 * CDIM + c];
            #pragma unroll
            for (int p = 0; p < PDIM; p++) {
                sk[p] += kn * we[p * NTOK + n];
                sv[p] += vn * wf[p * NTOK + n];
            }
        }
        #pragma unroll
        for (int p = 0; p < PDIM; p++) { s_klow[p][c] = sk[p]; s_vlow[p][c] = sv[p]; }
    }
    __syncthreads();

    // attn_sel: thread <-> (h, g); q token IDX_I=1, k token IDX_J=2
    {
        int h = tid >> 4, g = tid & 15;
        const float* krow = base + (size_t)2 * 3 * CDIM + CDIM + g * DDIM;
        const float* qrow = &s_q[1][h * DDIM];
        float s = 0.f;
        #pragma unroll
        for (int d = 0; d < DDIM; d++) s += qrow[d] * krow[d];
        s *= SCALE_F;
        attn_sel[((size_t)b * HDIM + h) * HDIM + g] = 1.f / (1.f + __expf(-s));
    }

    // reduced softmax attention + context: 64 active threads <-> (h, n)
    if (tid < HDIM * NTOK) {
        int h = tid >> 2, n = tid & 3;
        const float* qrow = &s_q[n][h * DDIM];
        float l[PDIM];
        #pragma unroll
        for (int p = 0; p < PDIM; p++) {
            float s = 0.f;
            #pragma unroll
            for (int d = 0; d < DDIM; d++) s += qrow[d] * s_klow[p][h * DDIM + d];
            l[p] = s * SCALE_F;
        }
        float mx = fmaxf(fmaxf(l[0], l[1]), fmaxf(l[2], l[3]));
        float e[PDIM], sum = 0.f;
        #pragma unroll
        for (int p = 0; p < PDIM; p++) { e[p] = __expf(l[p] - mx); sum += e[p]; }
        float inv = 1.f / sum;
        #pragma unroll
        for (int p = 0; p < PDIM; p++) e[p] *= inv;

        float* orow = g_ctx + ((size_t)b * NTOK + n) * CDIM + h * DDIM;
        #pragma unroll
        for (int d = 0; d < DDIM; d++) {
            float o = 0.f;
            #pragma unroll
            for (int p = 0; p < PDIM; p++) o += e[p] * s_vlow[p][h * DDIM + d];
            orow[d] = o;
        }
    }
}

// ---------------------------------------------------------------------------
extern "C" void kernel_launch(void* const* d_in, const int* in_sizes, int n_in,
                              void* d_out, int out_size)
{
    (void)in_sizes; (void)n_in; (void)out_size;
    const float* x      = (const float*)d_in[0];
    const float* W_qkv  = (const float*)d_in[1];
    const float* W_proj = (const float*)d_in[2];
    const float* b_proj = (const float*)d_in[3];
    const float* W_E    = (const float*)d_in[4];
    const float* W_F    = (const float*)d_in[5];

    float* out      = (float*)d_out;                       // [B*N*C]
    float* attn_sel = out + (size_t)MTOK * CDIM;           // [B*H*H]

    float* qkv_ptr = nullptr;
    float* ctx_ptr = nullptr;
    cudaGetSymbolAddress((void**)&qkv_ptr, g_qkv);
    cudaGetSymbolAddress((void**)&ctx_ptr, g_ctx);

    // K1: qkv = x @ W_qkv   [32768 x 3072]
    sgemm_kernel<false, false><<<dim3(3 * CDIM / 128, MTOK / 128), 256>>>(
        x, W_qkv, nullptr, qkv_ptr, MTOK, 3 * CDIM, CDIM);

    // K2: per-batch attention middle
    attn_mid_kernel<<<BDIM, 256>>>(W_E, W_F, attn_sel);

    // K3: out = ctx @ W_proj^T + b_proj   [32768 x 1024]
    sgemm_kernel<true, true><<<dim3(CDIM / 128, MTOK / 128), 256>>>(
        ctx_ptr, W_proj, b_proj, out, MTOK, CDIM, CDIM);
}

// round 4
// speedup vs baseline: 2.5320x; 2.5320x over previous
#include <cuda_runtime.h>

// ---------------------------------------------------------------------------
// Linformer block via mma.sync tf32 (HMMA; harness PTX target is compute_103,
// so tcgen05/'a'-features are unavailable):
//   K0: transpose W_qkv [1024,3072] -> g_Wt [3072,1024]
//   K1: qkv = x @ W_qkv          (tf32 mma.sync, cp.async pipeline)
//   K2: per-batch attention middle (fp32)
//   K3: out = ctx @ W_proj^T + b (same GEMM, W_proj already [N,K])
// ---------------------------------------------------------------------------

#define BDIM  8192
#define NTOK  4
#define CDIM  1024
#define HDIM  16
#define DDIM  64
#define PDIM  4
#define MTOK  (BDIM * NTOK)
#define SCALE_F 0.125f

__device__ float g_qkv[(size_t)MTOK * 3 * CDIM];
__device__ float g_ctx[(size_t)MTOK * CDIM];
__device__ float g_Wt [(size_t)3 * CDIM * CDIM];

// ------------------------------ GEMM config --------------------------------
#define BM 128
#define BN 128
#define BKC 32
#define NCH (CDIM / BKC)            // 32 k-chunks
#define RS 36                        // smem row stride in floats (conflict-free)
#define STAGE_FLOATS (256 * RS)      // 128 A rows + 128 B rows
#define STAGE_BYTES  (STAGE_FLOATS * 4)          // 36864
#define SMEM_DYN     (2 * STAGE_BYTES)           // 73728

__device__ __forceinline__ unsigned smem_u32(const void* p) {
    unsigned a;
    asm("{ .reg .u64 t; cvta.to.shared.u64 t, %1; cvt.u32.u64 %0, t; }"
        : "=r"(a) : "l"(p));
    return a;
}
__device__ __forceinline__ void cp16(unsigned saddr, const float* g) {
    asm volatile("cp.async.cg.shared.global [%0], [%1], 16;"
                 :: "r"(saddr), "l"(g) : "memory");
}
__device__ __forceinline__ void cp_commit() {
    asm volatile("cp.async.commit_group;" ::: "memory");
}
template<int N_>
__device__ __forceinline__ void cp_wait() {
    asm volatile("cp.async.wait_group %0;" :: "n"(N_) : "memory");
}
__device__ __forceinline__ unsigned f2tf(float f) {
    unsigned u; asm("cvt.rna.tf32.f32 %0, %1;" : "=r"(u) : "f"(f)); return u;
}
__device__ __forceinline__ void mma_tf32(float* d, const unsigned* a,
                                         const unsigned* b) {
    asm volatile(
        "mma.sync.aligned.m16n8k8.row.col.f32.tf32.tf32.f32 "
        "{%0,%1,%2,%3}, {%4,%5,%6,%7}, {%8,%9}, {%0,%1,%2,%3};"
        : "+f"(d[0]), "+f"(d[1]), "+f"(d[2]), "+f"(d[3])
        : "r"(a[0]), "r"(a[1]), "r"(a[2]), "r"(a[3]), "r"(b[0]), "r"(b[1]));
}

// ---------------------------------------------------------------------------
// C[M,Ncols] = A[M,1024] * B^T (+bias), B stored [Ncols,1024] row-major.
// ---------------------------------------------------------------------------
template<bool BIAS>
__global__ __launch_bounds__(256, 2)
void tf32_gemm(const float* __restrict__ A, const float* __restrict__ B,
               const float* __restrict__ bias, float* __restrict__ C, int Ncols)
{
    extern __shared__ float smf[];
    const unsigned sb = smem_u32(smf);
    const int tid = threadIdx.x;
    const int m0 = blockIdx.y * BM;
    const int n0 = blockIdx.x * BN;

    const int w  = tid >> 5;
    const int wm = w & 3;            // 0..3  -> m offset wm*32
    const int wn = w >> 2;           // 0..1  -> n offset wn*64
    const int ln = tid & 31;
    const int g  = ln >> 2;          // 0..7
    const int q  = ln & 3;           // 0..3

    // cp.async slot precompute: 2048 16B ops/chunk, 8 per thread (4 A + 4 B)
    const float* gA[4]; unsigned sA[4];
    const float* gB[4]; unsigned sB[4];
    #pragma unroll
    for (int i = 0; i < 4; i++) {
        int idx = tid + i * 256;          // 0..1023
        int row = idx >> 3, seg = idx & 7;
        gA[i] = A + (size_t)(m0 + row) * CDIM + seg * 4;
        sA[i] = sb + (row * RS + seg * 4) * 4;
        gB[i] = B + (size_t)(n0 + row) * CDIM + seg * 4;
        sB[i] = sb + ((128 + row) * RS + seg * 4) * 4;
    }

    #define ISSUE(ch) do { unsigned so = ((ch) & 1) * STAGE_BYTES;            \
        int ko = (ch) * BKC;                                                  \
        _Pragma("unroll") for (int i = 0; i < 4; i++) {                       \
            cp16(sA[i] + so, gA[i] + ko);                                     \
            cp16(sB[i] + so, gB[i] + ko); }                                    \
        cp_commit(); } while (0)

    float acc[2][8][4];
    #pragma unroll
    for (int mf = 0; mf < 2; mf++)
        #pragma unroll
        for (int nf = 0; nf < 8; nf++)
            #pragma unroll
            for (int i = 0; i < 4; i++) acc[mf][nf][i] = 0.f;

    ISSUE(0);

    const float* SaBase = smf + (wm * 32 + g) * RS;
    const float* SbBase = smf + (size_t)128 * RS + (wn * 64 + g) * RS;

    for (int s = 0; s < NCH; s++) {
        if (s + 1 < NCH) { ISSUE(s + 1); cp_wait<1>(); }
        else             { cp_wait<0>(); }
        __syncthreads();

        const float* Sa = SaBase + (s & 1) * STAGE_FLOATS;
        const float* Sb = SbBase + (s & 1) * STAGE_FLOATS;

        #pragma unroll
        for (int kk = 0; kk < 4; kk++) {
            const int kb = kk * 8 + q;
            unsigned a[2][4], b[8][2];
            #pragma unroll
            for (int mf = 0; mf < 2; mf++) {
                const float* p = Sa + mf * 16 * RS;
                a[mf][0] = f2tf(p[kb]);
                a[mf][1] = f2tf(p[8 * RS + kb]);
                a[mf][2] = f2tf(p[kb + 4]);
                a[mf][3] = f2tf(p[8 * RS + kb + 4]);
            }
            #pragma unroll
            for (int nf = 0; nf < 8; nf++) {
                const float* p = Sb + nf * 8 * RS;
                b[nf][0] = f2tf(p[kb]);
                b[nf][1] = f2tf(p[kb + 4]);
            }
            #pragma unroll
            for (int mf = 0; mf < 2; mf++)
                #pragma unroll
                for (int nf = 0; nf < 8; nf++)
                    mma_tf32(acc[mf][nf], a[mf], b[nf]);
        }
        __syncthreads();
    }

    // Epilogue: c0/c1 at (row, col..col+1); c2/c3 at (row+8, ...)
    const int mw = m0 + wm * 32 + g;
    const int nw = n0 + wn * 64 + 2 * q;
    #pragma unroll
    for (int mf = 0; mf < 2; mf++) {
        #pragma unroll
        for (int nf = 0; nf < 8; nf++) {
            int col = nw + nf * 8;
            float b0 = 0.f, b1 = 0.f;
            if (BIAS) { b0 = __ldg(bias + col); b1 = __ldg(bias + col + 1); }
            float* p0 = C + (size_t)(mw + mf * 16) * Ncols + col;
            float* p1 = p0 + (size_t)8 * Ncols;
            p0[0] = acc[mf][nf][0] + b0;  p0[1] = acc[mf][nf][1] + b1;
            p1[0] = acc[mf][nf][2] + b0;  p1[1] = acc[mf][nf][3] + b1;
        }
    }
    #undef ISSUE
}

// ---------------------------------------------------------------------------
// W_qkv transpose: [1024,3072] -> [3072,1024]
// ---------------------------------------------------------------------------
__global__ __launch_bounds__(256)
void transpose_kernel(const float* __restrict__ in, float* __restrict__ out)
{
    __shared__ float t[32][33];
    int bx = blockIdx.x * 32, by = blockIdx.y * 32;
    int x = threadIdx.x & 31, y = threadIdx.x >> 5;
    #pragma unroll
    for (int i = 0; i < 32; i += 8)
        t[y + i][x] = in[(size_t)(by + y + i) * (3 * CDIM) + bx + x];
    __syncthreads();
    #pragma unroll
    for (int i = 0; i < 32; i += 8)
        out[(size_t)(bx + y + i) * CDIM + by + x] = t[x][y + i];
}

// ---------------------------------------------------------------------------
// Middle kernel: one CTA per batch.
// ---------------------------------------------------------------------------
__global__ __launch_bounds__(256)
void attn_mid_kernel(const float* __restrict__ W_E, const float* __restrict__ W_F,
                     float* __restrict__ attn_sel)
{
    __shared__ float s_q[NTOK][CDIM];
    __shared__ float s_klow[PDIM][CDIM];
    __shared__ float s_vlow[PDIM][CDIM];

    const int b = blockIdx.x;
    const int tid = threadIdx.x;
    const float* base = g_qkv + (size_t)b * NTOK * 3 * CDIM;

    for (int i = tid; i < NTOK * CDIM / 4; i += 256) {
        int n = i >> 8;
        int c4 = (i & 255) << 2;
        *reinterpret_cast<float4*>(&s_q[n][c4]) =
            *reinterpret_cast<const float4*>(base + (size_t)n * 3 * CDIM + c4);
    }
    float we[PDIM * NTOK], wf[PDIM * NTOK];
    #pragma unroll
    for (int i = 0; i < PDIM * NTOK; i++) { we[i] = __ldg(W_E + i); wf[i] = __ldg(W_F + i); }

    for (int c = tid; c < CDIM; c += 256) {
        float sk[PDIM] = {0.f,0.f,0.f,0.f}, sv[PDIM] = {0.f,0.f,0.f,0.f};
        #pragma unroll
        for (int n = 0; n < NTOK; n++) {
            float kn = base[(size_t)n * 3 * CDIM + CDIM + c];
            float vn = base[(size_t)n * 3 * CDIM + 2 * CDIM + c];
            #pragma unroll
            for (int p = 0; p < PDIM; p++) {
                sk[p] += kn * we[p * NTOK + n];
                sv[p] += vn * wf[p * NTOK + n];
            }
        }
        #pragma unroll
        for (int p = 0; p < PDIM; p++) { s_klow[p][c] = sk[p]; s_vlow[p][c] = sv[p]; }
    }
    __syncthreads();

    {
        int h = tid >> 4, gg = tid & 15;
        const float* krow = base + (size_t)2 * 3 * CDIM + CDIM + gg * DDIM;
        const float* qrow = &s_q[1][h * DDIM];
        float s = 0.f;
        #pragma unroll
        for (int d = 0; d < DDIM; d++) s += qrow[d] * krow[d];
        s *= SCALE_F;
        attn_sel[((size_t)b * HDIM + h) * HDIM + gg] = 1.f / (1.f + __expf(-s));
    }
    if (tid < HDIM * NTOK) {
        int h = tid >> 2, n = tid & 3;
        const float* qrow = &s_q[n][h * DDIM];
        float l[PDIM];
        #pragma unroll
        for (int p = 0; p < PDIM; p++) {
            float s = 0.f;
            #pragma unroll
            for (int d = 0; d < DDIM; d++) s += qrow[d] * s_klow[p][h * DDIM + d];
            l[p] = s * SCALE_F;
        }
        float mx = fmaxf(fmaxf(l[0], l[1]), fmaxf(l[2], l[3]));
        float e[PDIM], sum = 0.f;
        #pragma unroll
        for (int p = 0; p < PDIM; p++) { e[p] = __expf(l[p] - mx); sum += e[p]; }
        float inv = 1.f / sum;
        #pragma unroll
        for (int p = 0; p < PDIM; p++) e[p] *= inv;
        float* orow = g_ctx + ((size_t)b * NTOK + n) * CDIM + h * DDIM;
        #pragma unroll
        for (int d = 0; d < DDIM; d++) {
            float o = 0.f;
            #pragma unroll
            for (int p = 0; p < PDIM; p++) o += e[p] * s_vlow[p][h * DDIM + d];
            orow[d] = o;
        }
    }
}

// ---------------------------------------------------------------------------
extern "C" void kernel_launch(void* const* d_in, const int* in_sizes, int n_in,
                              void* d_out, int out_size)
{
    (void)in_sizes; (void)n_in; (void)out_size;
    const float* x      = (const float*)d_in[0];
    const float* W_qkv  = (const float*)d_in[1];
    const float* W_proj = (const float*)d_in[2];
    const float* b_proj = (const float*)d_in[3];
    const float* W_E    = (const float*)d_in[4];
    const float* W_F    = (const float*)d_in[5];

    float* out      = (float*)d_out;
    float* attn_sel = out + (size_t)MTOK * CDIM;

    float *qkv_ptr = nullptr, *ctx_ptr = nullptr, *wt_ptr = nullptr;
    cudaGetSymbolAddress((void**)&qkv_ptr, g_qkv);
    cudaGetSymbolAddress((void**)&ctx_ptr, g_ctx);
    cudaGetSymbolAddress((void**)&wt_ptr,  g_Wt);

    cudaFuncSetAttribute(tf32_gemm<false>,
                         cudaFuncAttributeMaxDynamicSharedMemorySize, SMEM_DYN);
    cudaFuncSetAttribute(tf32_gemm<true>,
                         cudaFuncAttributeMaxDynamicSharedMemorySize, SMEM_DYN);

    transpose_kernel<<<dim3(3 * CDIM / 32, CDIM / 32), 256>>>(W_qkv, wt_ptr);

    tf32_gemm<false><<<dim3(3 * CDIM / BN, MTOK / BM), 256, SMEM_DYN>>>(
        x, wt_ptr, nullptr, qkv_ptr, 3 * CDIM);

    attn_mid_kernel<<<BDIM, 256>>>(W_E, W_F, attn_sel);

    tf32_gemm<true><<<dim3(CDIM / BN, MTOK / BM), 256, SMEM_DYN>>>(
        ctx_ptr, W_proj, b_proj, out, CDIM);
}

// round 6
// speedup vs baseline: 2.6982x; 1.0656x over previous
#include <cuda_runtime.h>

// ---------------------------------------------------------------------------
// Linformer block via mma.sync tf32 (HMMA; compute_103 PTX target, no tcgen05).
// R5: all operands pre-rounded to tf32 in gmem (zero in-loop CVT), fragment
// loads vectorized to conflict-free LDS.64 via k-permutation, RS=40.
//   K0a: transpose+round W_qkv -> g_Wt [3072,1024]
//   K0b: round W_proj -> g_Wpt, round x -> g_xtf
//   K1:  qkv = xtf @ Wt^T        (tf32 mma.sync, cp.async double buffer)
//   K2:  per-batch attention middle (fp32, ctx stored rounded)
//   K3:  out = ctx @ Wpt^T + b
// ---------------------------------------------------------------------------

#define BDIM  8192
#define NTOK  4
#define CDIM  1024
#define HDIM  16
#define DDIM  64
#define PDIM  4
#define MTOK  (BDIM * NTOK)
#define SCALE_F 0.125f

__device__ float g_qkv[(size_t)MTOK * 3 * CDIM];
__device__ float g_ctx[(size_t)MTOK * CDIM];
__device__ float g_xtf[(size_t)MTOK * CDIM];
__device__ float g_Wt [(size_t)3 * CDIM * CDIM];
__device__ float g_Wpt[(size_t)CDIM * CDIM];

// ------------------------------ GEMM config --------------------------------
#define BM 128
#define BN 128
#define BKC 32
#define NCH (CDIM / BKC)             // 32 k-chunks
#define RS 40                         // floats per smem row (LDS.64 conflict-free)
#define STAGE_FLOATS (256 * RS)       // 128 A rows + 128 B rows
#define STAGE_BYTES  (STAGE_FLOATS * 4)          // 40960
#define SMEM_DYN     (2 * STAGE_BYTES)           // 81920

__device__ __forceinline__ unsigned smem_u32(const void* p) {
    unsigned a;
    asm("{ .reg .u64 t; cvta.to.shared.u64 t, %1; cvt.u32.u64 %0, t; }"
        : "=r"(a) : "l"(p));
    return a;
}
__device__ __forceinline__ void cp16(unsigned saddr, const float* g) {
    asm volatile("cp.async.cg.shared.global [%0], [%1], 16;"
                 :: "r"(saddr), "l"(g) : "memory");
}
__device__ __forceinline__ void cp_commit() {
    asm volatile("cp.async.commit_group;" ::: "memory");
}
template<int N_>
__device__ __forceinline__ void cp_wait() {
    asm volatile("cp.async.wait_group %0;" :: "n"(N_) : "memory");
}
__device__ __forceinline__ unsigned f2tf(float f) {
    unsigned u; asm("cvt.rna.tf32.f32 %0, %1;" : "=r"(u) : "f"(f)); return u;
}
__device__ __forceinline__ float f2tf_f(float f) {
    return __uint_as_float(f2tf(f));
}
__device__ __forceinline__ void mma_tf32(float* d, const unsigned* a,
                                         const unsigned* b) {
    asm volatile(
        "mma.sync.aligned.m16n8k8.row.col.f32.tf32.tf32.f32 "
        "{%0,%1,%2,%3}, {%4,%5,%6,%7}, {%8,%9}, {%0,%1,%2,%3};"
        : "+f"(d[0]), "+f"(d[1]), "+f"(d[2]), "+f"(d[3])
        : "r"(a[0]), "r"(a[1]), "r"(a[2]), "r"(a[3]), "r"(b[0]), "r"(b[1]));
}

// ---------------------------------------------------------------------------
// C[M,Ncols] = A[M,1024] * B^T (+bias); A,B pre-rounded tf32 bit patterns.
// B stored [Ncols,1024] row-major. 128x128 tile, 8 warps (4m x 2n), 32x64/warp.
// k-permutation: within each 32-k chunk, slice kk consumes logical
// k = kk*8 + 2q + {0,1}; lane (g,q) loads one float2 per row.
// ---------------------------------------------------------------------------
template<bool BIAS>
__global__ __launch_bounds__(256, 2)
void tf32_gemm(const float* __restrict__ A, const float* __restrict__ B,
               const float* __restrict__ bias, float* __restrict__ C, int Ncols)
{
    extern __shared__ float smf[];
    const unsigned sb = smem_u32(smf);
    const int tid = threadIdx.x;
    const int m0 = blockIdx.y * BM;
    const int n0 = blockIdx.x * BN;

    const int w  = tid >> 5;
    const int wm = w & 3;             // m offset wm*32
    const int wn = w >> 2;            // n offset wn*64
    const int ln = tid & 31;
    const int g  = ln >> 2;           // 0..7
    const int q  = ln & 3;            // 0..3

    // cp.async slots: 1024 16B segs/chunk (A) + 1024 (B) -> 4+4 per thread
    const float* gA[4]; unsigned sA[4];
    const float* gB[4]; unsigned sB[4];
    #pragma unroll
    for (int i = 0; i < 4; i++) {
        int idx = tid + i * 256;           // 0..1023
        int row = idx >> 3, seg = idx & 7;
        gA[i] = A + (size_t)(m0 + row) * CDIM + seg * 4;
        sA[i] = sb + (row * RS + seg * 4) * 4;
        gB[i] = B + (size_t)(n0 + row) * CDIM + seg * 4;
        sB[i] = sb + ((128 + row) * RS + seg * 4) * 4;
    }

    #define ISSUE(ch) do { unsigned so = ((ch) & 1) * STAGE_BYTES;            \
        int ko = (ch) * BKC;                                                  \
        _Pragma("unroll") for (int i = 0; i < 4; i++) {                       \
            cp16(sA[i] + so, gA[i] + ko);                                     \
            cp16(sB[i] + so, gB[i] + ko); }                                    \
        cp_commit(); } while (0)

    float acc[2][8][4];
    #pragma unroll
    for (int mf = 0; mf < 2; mf++)
        #pragma unroll
        for (int nf = 0; nf < 8; nf++)
            #pragma unroll
            for (int i = 0; i < 4; i++) acc[mf][nf][i] = 0.f;

    ISSUE(0);

    const float* SaBase = smf + (wm * 32 + g) * RS;
    const float* SbBase = smf + (128 + wn * 64 + g) * RS;

    for (int s = 0; s < NCH; s++) {
        if (s + 1 < NCH) { ISSUE(s + 1); cp_wait<1>(); }
        else             { cp_wait<0>(); }
        __syncthreads();

        const float* Sa = SaBase + (s & 1) * STAGE_FLOATS;
        const float* Sb = SbBase + (s & 1) * STAGE_FLOATS;

        #pragma unroll
        for (int kk = 0; kk < 4; kk++) {
            const int ko = kk * 8 + 2 * q;
            // A fragments: rows g, g+8 (mf=0) / g+16, g+24 (mf=1)
            float2 a0 = *reinterpret_cast<const float2*>(Sa + ko);
            float2 a1 = *reinterpret_cast<const float2*>(Sa + 8 * RS + ko);
            float2 a2 = *reinterpret_cast<const float2*>(Sa + 16 * RS + ko);
            float2 a3 = *reinterpret_cast<const float2*>(Sa + 24 * RS + ko);
            unsigned af[2][4];
            af[0][0] = __float_as_uint(a0.x); af[0][1] = __float_as_uint(a1.x);
            af[0][2] = __float_as_uint(a0.y); af[0][3] = __float_as_uint(a1.y);
            af[1][0] = __float_as_uint(a2.x); af[1][1] = __float_as_uint(a3.x);
            af[1][2] = __float_as_uint(a2.y); af[1][3] = __float_as_uint(a3.y);

            unsigned bf[8][2];
            #pragma unroll
            for (int nf = 0; nf < 8; nf++) {
                float2 bv = *reinterpret_cast<const float2*>(Sb + nf * 8 * RS + ko);
                bf[nf][0] = __float_as_uint(bv.x);
                bf[nf][1] = __float_as_uint(bv.y);
            }
            #pragma unroll
            for (int mf = 0; mf < 2; mf++)
                #pragma unroll
                for (int nf = 0; nf < 8; nf++)
                    mma_tf32(acc[mf][nf], af[mf], bf[nf]);
        }
        __syncthreads();
    }

    // Epilogue: lane (g,q) holds D[g][2q],D[g][2q+1],D[g+8][2q],D[g+8][2q+1]
    const int mw = m0 + wm * 32 + g;
    const int nw = n0 + wn * 64 + 2 * q;
    #pragma unroll
    for (int mf = 0; mf < 2; mf++) {
        #pragma unroll
        for (int nf = 0; nf < 8; nf++) {
            int col = nw + nf * 8;
            float b0 = 0.f, b1 = 0.f;
            if (BIAS) { b0 = __ldg(bias + col); b1 = __ldg(bias + col + 1); }
            float* p0 = C + (size_t)(mw + mf * 16) * Ncols + col;
            float* p1 = p0 + (size_t)8 * Ncols;
            p0[0] = acc[mf][nf][0] + b0;  p0[1] = acc[mf][nf][1] + b1;
            p1[0] = acc[mf][nf][2] + b0;  p1[1] = acc[mf][nf][3] + b1;
        }
    }
    #undef ISSUE
}

// ---------------------------------------------------------------------------
// W_qkv transpose + tf32 round: [1024,3072] -> [3072,1024]
// ---------------------------------------------------------------------------
__global__ __launch_bounds__(256)
void transpose_kernel(const float* __restrict__ in, float* __restrict__ out)
{
    __shared__ float t[32][33];
    int bx = blockIdx.x * 32, by = blockIdx.y * 32;
    int x = threadIdx.x & 31, y = threadIdx.x >> 5;
    #pragma unroll
    for (int i = 0; i < 32; i += 8)
        t[y + i][x] = f2tf_f(in[(size_t)(by + y + i) * (3 * CDIM) + bx + x]);
    __syncthreads();
    #pragma unroll
    for (int i = 0; i < 32; i += 8)
        out[(size_t)(bx + y + i) * CDIM + by + x] = t[x][y + i];
}

// ---------------------------------------------------------------------------
// Elementwise tf32 round-copy (float4 grid-stride)
// ---------------------------------------------------------------------------
__global__ __launch_bounds__(256)
void round_kernel(const float4* __restrict__ in, float4* __restrict__ out, int n4)
{
    for (int i = blockIdx.x * blockDim.x + threadIdx.x; i < n4;
         i += gridDim.x * blockDim.x) {
        float4 v = in[i];
        v.x = f2tf_f(v.x); v.y = f2tf_f(v.y);
        v.z = f2tf_f(v.z); v.w = f2tf_f(v.w);
        out[i] = v;
    }
}

// ---------------------------------------------------------------------------
// Middle kernel: one CTA per batch. ctx stored tf32-rounded (GEMM2 A operand).
// ---------------------------------------------------------------------------
__global__ __launch_bounds__(256)
void attn_mid_kernel(const float* __restrict__ W_E, const float* __restrict__ W_F,
                     float* __restrict__ attn_sel)
{
    __shared__ float s_q[NTOK][CDIM];
    __shared__ float s_klow[PDIM][CDIM];
    __shared__ float s_vlow[PDIM][CDIM];

    const int b = blockIdx.x;
    const int tid = threadIdx.x;
    const float* base = g_qkv + (size_t)b * NTOK * 3 * CDIM;

    for (int i = tid; i < NTOK * CDIM / 4; i += 256) {
        int n = i >> 8;
        int c4 = (i & 255) << 2;
        *reinterpret_cast<float4*>(&s_q[n][c4]) =
            *reinterpret_cast<const float4*>(base + (size_t)n * 3 * CDIM + c4);
    }
    float we[PDIM * NTOK], wf[PDIM * NTOK];
    #pragma unroll
    for (int i = 0; i < PDIM * NTOK; i++) { we[i] = __ldg(W_E + i); wf[i] = __ldg(W_F + i); }

    for (int c = tid; c < CDIM; c += 256) {
        float sk[PDIM] = {0.f,0.f,0.f,0.f}, sv[PDIM] = {0.f,0.f,0.f,0.f};
        #pragma unroll
        for (int n = 0; n < NTOK; n++) {
            float kn = base[(size_t)n * 3 * CDIM + CDIM + c];
            float vn = base[(size_t)n * 3 * CDIM + 2 * CDIM + c];
            #pragma unroll
            for (int p = 0; p < PDIM; p++) {
                sk[p] += kn * we[p * NTOK + n];
                sv[p] += vn * wf[p * NTOK + n];
            }
        }
        #pragma unroll
        for (int p = 0; p < PDIM; p++) { s_klow[p][c] = sk[p]; s_vlow[p][c] = sv[p]; }
    }
    __syncthreads();

    {
        int h = tid >> 4, gg = tid & 15;
        const float* krow = base + (size_t)2 * 3 * CDIM + CDIM + gg * DDIM;
        const float* qrow = &s_q[1][h * DDIM];
        float s = 0.f;
        #pragma unroll
        for (int d = 0; d < DDIM; d++) s += qrow[d] * krow[d];
        s *= SCALE_F;
        attn_sel[((size_t)b * HDIM + h) * HDIM + gg] = 1.f / (1.f + __expf(-s));
    }
    if (tid < HDIM * NTOK) {
        int h = tid >> 2, n = tid & 3;
        const float* qrow = &s_q[n][h * DDIM];
        float l[PDIM];
        #pragma unroll
        for (int p = 0; p < PDIM; p++) {
            float s = 0.f;
            #pragma unroll
            for (int d = 0; d < DDIM; d++) s += qrow[d] * s_klow[p][h * DDIM + d];
            l[p] = s * SCALE_F;
        }
        float mx = fmaxf(fmaxf(l[0], l[1]), fmaxf(l[2], l[3]));
        float e[PDIM], sum = 0.f;
        #pragma unroll
        for (int p = 0; p < PDIM; p++) { e[p] = __expf(l[p] - mx); sum += e[p]; }
        float inv = 1.f / sum;
        #pragma unroll
        for (int p = 0; p < PDIM; p++) e[p] *= inv;
        float* orow = g_ctx + ((size_t)b * NTOK + n) * CDIM + h * DDIM;
        #pragma unroll
        for (int d = 0; d < DDIM; d++) {
            float o = 0.f;
            #pragma unroll
            for (int p = 0; p < PDIM; p++) o += e[p] * s_vlow[p][h * DDIM + d];
            orow[d] = f2tf_f(o);
        }
    }
}

// ---------------------------------------------------------------------------
extern "C" void kernel_launch(void* const* d_in, const int* in_sizes, int n_in,
                              void* d_out, int out_size)
{
    (void)in_sizes; (void)n_in; (void)out_size;
    const float* x      = (const float*)d_in[0];
    const float* W_qkv  = (const float*)d_in[1];
    const float* W_proj = (const float*)d_in[2];
    const float* b_proj = (const float*)d_in[3];
    const float* W_E    = (const float*)d_in[4];
    const float* W_F    = (const float*)d_in[5];

    float* out      = (float*)d_out;
    float* attn_sel = out + (size_t)MTOK * CDIM;

    float *qkv_ptr, *ctx_ptr, *xtf_ptr, *wt_ptr, *wpt_ptr;
    cudaGetSymbolAddress((void**)&qkv_ptr, g_qkv);
    cudaGetSymbolAddress((void**)&ctx_ptr, g_ctx);
    cudaGetSymbolAddress((void**)&xtf_ptr, g_xtf);
    cudaGetSymbolAddress((void**)&wt_ptr,  g_Wt);
    cudaGetSymbolAddress((void**)&wpt_ptr, g_Wpt);

    cudaFuncSetAttribute(tf32_gemm<false>,
                         cudaFuncAttributeMaxDynamicSharedMemorySize, SMEM_DYN);
    cudaFuncSetAttribute(tf32_gemm<true>,
                         cudaFuncAttributeMaxDynamicSharedMemorySize, SMEM_DYN);

    // K0: operand pre-rounding
    transpose_kernel<<<dim3(3 * CDIM / 32, CDIM / 32), 256>>>(W_qkv, wt_ptr);
    round_kernel<<<1024, 256>>>((const float4*)W_proj, (float4*)wpt_ptr,
                                CDIM * CDIM / 4);
    round_kernel<<<8192, 256>>>((const float4*)x, (float4*)xtf_ptr,
                                MTOK * CDIM / 4);

    // K1: qkv = xtf @ Wt^T
    tf32_gemm<false><<<dim3(3 * CDIM / BN, MTOK / BM), 256, SMEM_DYN>>>(
        xtf_ptr, wt_ptr, nullptr, qkv_ptr, 3 * CDIM);

    // K2: attention middle (ctx rounded on store)
    attn_mid_kernel<<<BDIM, 256>>>(W_E, W_F, attn_sel);

    // K3: out = ctx @ Wpt^T + b
    tf32_gemm<true><<<dim3(CDIM / BN, MTOK / BM), 256, SMEM_DYN>>>(
        ctx_ptr, wpt_ptr, b_proj, out, CDIM);
}